// round 15
// baseline (speedup 1.0000x reference)
#include <cuda_runtime.h>
#include <cuda_fp16.h>
#include <math.h>

// ---------------------------------------------------------------------------
// Problem constants
// ---------------------------------------------------------------------------
#define BB    4
#define BPTT  16
#define PRED  4
#define SS    20
#define VV    512
#define EE    256
#define NHH   8
#define HEADD 32
#define HIDD  512
#define NEE   512
#define FF    80

#define FVE   ((size_t)FF * VV * EE)
#define FVH   ((size_t)FF * VV * HIDD)
#define SCORE_SIZE (BB * NEE * PRED * VV)
#define NROWS (BB * PRED * VV)

#define WEE27 1769472ull                 // 27*256*256
#define WEH27 3538944ull                 // 27*256*512
#define WT_LAYER (4ull*WEE27 + 2ull*WEH27)
#define WT_TOTAL (4ull*WT_LAYER + WEE27)

// ---------------------------------------------------------------------------
// Scratch (allocation-free: __device__ globals)
// ---------------------------------------------------------------------------
__device__ float g_x[FVE];
__device__ float g_q[FVE];
__device__ float g_k[FVE];
__device__ float g_v[FVE];
__device__ float g_logits[FVH];
__device__ float g_rowloss[NROWS];
__device__ __half g_ah[FVE];
__device__ __half g_al[FVE];
__device__ __half g_bh[FVH];
__device__ __half g_bl[FVH];
__device__ __half g_wth[WT_TOTAL];
__device__ __half g_wtl[WT_TOTAL];

// ---------------------------------------------------------------------------
// PTX helpers (baseline sm_103-compatible: cp.async, ldmatrix, mma.sync)
// ---------------------------------------------------------------------------
__device__ __forceinline__ unsigned smem_u32(const void* p) {
    unsigned a;
    asm("{ .reg .u64 t; cvta.to.shared.u64 t, %1; cvt.u32.u64 %0, t; }"
        : "=r"(a) : "l"(p));
    return a;
}
__device__ __forceinline__ void cp_async16z(unsigned dst, const void* src, int ssz) {
    asm volatile("cp.async.cg.shared.global [%0], [%1], 16, %2;"
                 :: "r"(dst), "l"(src), "r"(ssz) : "memory");
}
__device__ __forceinline__ void ldsm4(unsigned* r, unsigned addr) {
    asm volatile("ldmatrix.sync.aligned.m8n8.x4.shared.b16 {%0,%1,%2,%3}, [%4];"
                 : "=r"(r[0]), "=r"(r[1]), "=r"(r[2]), "=r"(r[3]) : "r"(addr));
}
__device__ __forceinline__ void mma16816(float* d, const unsigned* a, const unsigned* b) {
    asm volatile(
        "mma.sync.aligned.m16n8k16.row.col.f32.f16.f16.f32 "
        "{%0,%1,%2,%3}, {%4,%5,%6,%7}, {%8,%9}, {%0,%1,%2,%3};"
        : "+f"(d[0]), "+f"(d[1]), "+f"(d[2]), "+f"(d[3])
        : "r"(a[0]), "r"(a[1]), "r"(a[2]), "r"(a[3]), "r"(b[0]), "r"(b[1]));
}

// ---------------------------------------------------------------------------
// Weight transpose + fp16 split:  w[27][Cin][Cout] f32 -> wt[27][Cout][Cin] hi/lo
// ---------------------------------------------------------------------------
__global__ void wconv_kernel(const float* __restrict__ w,
                             __half* __restrict__ th,
                             __half* __restrict__ tl,
                             int Cin, int Cout)
{
    size_t n = (size_t)27 * Cin * Cout;
    size_t i = (size_t)blockIdx.x * 256 + threadIdx.x;
    if (i >= n) return;
    int pc = Cin * Cout;
    int o = (int)(i / pc);
    int r = (int)(i - (size_t)o * pc);
    int co = r / Cin, ci = r - co * Cin;
    float x = w[((size_t)o * Cin + ci) * Cout + co];
    __half h = __float2half(x);
    th[i] = h;
    tl[i] = __float2half(x - __half2float(h));
}

// ---------------------------------------------------------------------------
// Embedding
// ---------------------------------------------------------------------------
__global__ void embed_kernel(const int* __restrict__ code,
                             const float* __restrict__ emb,
                             const float* __restrict__ pos,
                             float* __restrict__ x)
{
    size_t idx = (size_t)blockIdx.x * blockDim.x + threadIdx.x;
    if (idx >= FVE) return;
    int e = (int)(idx & 255);
    int v = (int)((idx >> 8) & 511);
    int f = (int)(idx >> 17);
    int b = f / SS, s = f % SS;
    int tok = (s < BPTT) ? code[((b * BPTT + s) << 9) + v] : NEE;
    x[idx] = emb[tok * EE + e] + pos[s * EE + e];
}

// ---------------------------------------------------------------------------
// LayerNorm; writes f32 and/or fp16 hi/lo pair
// ---------------------------------------------------------------------------
__global__ void ln_kernel(const float* __restrict__ in,
                          float* __restrict__ outF,
                          __half* __restrict__ outH,
                          __half* __restrict__ outL,
                          const float* __restrict__ sc, const float* __restrict__ bi,
                          int rows)
{
    int wid  = (int)((blockIdx.x * blockDim.x + threadIdx.x) >> 5);
    int lane = threadIdx.x & 31;
    if (wid >= rows) return;
    const float* p = in + (size_t)wid * EE;
    float v8[8];
    float s = 0.f, sq = 0.f;
#pragma unroll
    for (int i = 0; i < 8; ++i) {
        float xv = p[lane + i * 32];
        v8[i] = xv; s += xv; sq = fmaf(xv, xv, sq);
    }
#pragma unroll
    for (int off = 16; off > 0; off >>= 1) {
        s  += __shfl_xor_sync(0xffffffffu, s, off);
        sq += __shfl_xor_sync(0xffffffffu, sq, off);
    }
    float m   = s * (1.f / 256.f);
    float var = sq * (1.f / 256.f) - m * m;
    if (var < 0.f) var = 0.f;
    float inv = rsqrtf(var + 1e-5f);
#pragma unroll
    for (int i = 0; i < 8; ++i) {
        int e = lane + i * 32;
        float r = (v8[i] - m) * inv * sc[e] + bi[e];
        size_t oi = (size_t)wid * EE + e;
        if (outF) outF[oi] = r;
        if (outH) {
            __half h = __float2half(r);
            outH[oi] = h;
            outL[oi] = __float2half(r - __half2float(h));
        }
    }
}

// ---------------------------------------------------------------------------
// Tensor-core (mma.sync fp16) 3D conv, 3x3x3 SAME, fp16x3 split precision,
// per-chunk RN accumulator drain (bounds mma RZ bias), 2-STAGE cp.async
// PIPELINE: chunk k+1 stages into the alternate smem buffer under chunk k's
// compute (wait_group 1 completes k, keeps k+1 in flight).
//   CTA: 256 thr (8 warps), tile M=128 x N=64; warp tile 32x32.
//   K loop = 27 taps x Cin/64 chunks.
// ---------------------------------------------------------------------------
#define APAD 144                           // bytes per smem row (72 halves)
#define AH_OFF 0
#define AL_OFF (128 * APAD)                // 18432
#define BH_OFF (2 * 128 * APAD)            // 36864
#define BL_OFF (BH_OFF + 64 * APAD)        // 46080
#define STG_STRIDE (BL_OFF + 64 * APAD)    // 55296
#define TC_SMEM_BYTES (2 * STG_STRIDE)     // 110592

__global__ void __launch_bounds__(256, 1)
conv3d_mma_kernel(const __half* __restrict__ xh,
                  const __half* __restrict__ xl,
                  const __half* __restrict__ wth,
                  const __half* __restrict__ wtl,
                  const float* __restrict__ bias, const float* __restrict__ residual,
                  float* __restrict__ yf,
                  __half* __restrict__ yh, __half* __restrict__ yl,
                  int Cin, int Cout, int do_gelu)
{
    extern __shared__ char smem[];
    unsigned sb = smem_u32(smem);
    const int t = threadIdx.x, w = t >> 5, lane = t & 31;
    const int wm = w & 3, wn = w >> 2;      // warp covers rows wm*32, cols wn*32
    const int f = blockIdx.x, co0 = blockIdx.y * 64, v0 = blockIdx.z * 128;

    // A staging: thread t -> tile row t/2, 32-half part t&1
    const int arow = t >> 1, apart = t & 1;
    const int av = v0 + arow, vz = av >> 6, vy = (av >> 3) & 7, vx = av & 7;
    // B staging: thread t -> cout row t/4, quads (t&3)*2..+1
    const int brow = t >> 2, bq0 = (t & 3) * 2;

    float acc[2][4][4], mst[2][4][4];
#pragma unroll
    for (int mt = 0; mt < 2; ++mt)
#pragma unroll
        for (int nt = 0; nt < 4; ++nt)
#pragma unroll
            for (int q = 0; q < 4; ++q) { acc[mt][nt][q] = 0.f; mst[mt][nt][q] = 0.f; }

    // ldmatrix lane base offsets (relative to stage base)
    const int rA = ((lane >> 3) & 1) * 8 + (lane & 7);
    const int cA = (lane >> 4) * 16;
    unsigned oAh[2], oAl[2];
#pragma unroll
    for (int mt = 0; mt < 2; ++mt) {
        unsigned off = (unsigned)(wm * 32 + mt * 16 + rA) * APAD + cA;
        oAh[mt] = AH_OFF + off;
        oAl[mt] = AL_OFF + off;
    }
    const int rB = ((lane >> 4) & 1) * 8 + (lane & 7);
    const int cB = ((lane >> 3) & 1) * 16;
    unsigned oBh[2], oBl[2];
#pragma unroll
    for (int nt2 = 0; nt2 < 2; ++nt2) {
        unsigned off = (unsigned)(wn * 32 + nt2 * 16 + rB) * APAD + cB;
        oBh[nt2] = BH_OFF + off;
        oBl[nt2] = BL_OFF + off;
    }

    const int ncc = Cin >> 6;
    const int nchunks = 27 * ncc;

    // staging helper: stage chunk ch into buffer base sbase; one commit_group
    auto stage_chunk = [&](int ch, unsigned sbase) {
        int o = ch / ncc, c = ch - o * ncc;
        int dz = o / 9 - 1, dy = (o % 9) / 3 - 1, dx = o % 3 - 1;
        int zz = vz + dz, yy = vy + dy, xx = vx + dx;
        int ok = ((unsigned)zz < 8u) && ((unsigned)yy < 8u) && ((unsigned)xx < 8u);
        size_t abase = ((size_t)f * VV + (size_t)(zz * 64 + yy * 8 + xx)) * Cin
                       + (size_t)c * 64 + apart * 32;
        const __half* sah = ok ? (xh + abase) : xh;
        const __half* sal = ok ? (xl + abase) : xl;
        int ssz = ok ? 16 : 0;
        unsigned dah = sbase + AH_OFF + (unsigned)arow * APAD + apart * 64;
        unsigned dal = sbase + AL_OFF + (unsigned)arow * APAD + apart * 64;
#pragma unroll
        for (int i = 0; i < 4; ++i) {
            cp_async16z(dah + i * 16, sah + i * 8, ssz);
            cp_async16z(dal + i * 16, sal + i * 8, ssz);
        }
        size_t bbase = ((size_t)o * Cout + (size_t)(co0 + brow)) * Cin + (size_t)c * 64;
        unsigned dbh = sbase + BH_OFF + (unsigned)brow * APAD;
        unsigned dbl = sbase + BL_OFF + (unsigned)brow * APAD;
#pragma unroll
        for (int q2 = 0; q2 < 2; ++q2) {
            int i = bq0 + q2;
            cp_async16z(dbh + i * 16, wth + bbase + i * 8, 16);
            cp_async16z(dbl + i * 16, wtl + bbase + i * 8, 16);
        }
        asm volatile("cp.async.commit_group;" ::: "memory");
    };

    // ---- prologue: stage chunk 0
    stage_chunk(0, sb);

    for (int ch = 0; ch < nchunks; ++ch) {
        if (ch + 1 < nchunks) {
            stage_chunk(ch + 1, sb + (unsigned)((ch + 1) & 1) * STG_STRIDE);
            asm volatile("cp.async.wait_group 1;" ::: "memory");
        } else {
            asm volatile("cp.async.wait_group 0;" ::: "memory");
        }
        __syncthreads();          // chunk ch data visible to all threads

        unsigned sbase = sb + (unsigned)(ch & 1) * STG_STRIDE;

        // ---- compute: 4 k16 steps x (2 mt x 4 nt) x 3 terms
#pragma unroll
        for (int ks = 0; ks < 4; ++ks) {
            unsigned kb = (unsigned)ks * 32;
            unsigned fAh[2][4], fAl[2][4], fBh[4][2], fBl[4][2];
#pragma unroll
            for (int mt = 0; mt < 2; ++mt) {
                ldsm4(fAh[mt], sbase + oAh[mt] + kb);
                ldsm4(fAl[mt], sbase + oAl[mt] + kb);
            }
#pragma unroll
            for (int nt2 = 0; nt2 < 2; ++nt2) {
                unsigned r4[4];
                ldsm4(r4, sbase + oBh[nt2] + kb);
                fBh[nt2 * 2][0] = r4[0]; fBh[nt2 * 2][1] = r4[1];
                fBh[nt2 * 2 + 1][0] = r4[2]; fBh[nt2 * 2 + 1][1] = r4[3];
                ldsm4(r4, sbase + oBl[nt2] + kb);
                fBl[nt2 * 2][0] = r4[0]; fBl[nt2 * 2][1] = r4[1];
                fBl[nt2 * 2 + 1][0] = r4[2]; fBl[nt2 * 2 + 1][1] = r4[3];
            }
#pragma unroll
            for (int mt = 0; mt < 2; ++mt)
#pragma unroll
                for (int nt = 0; nt < 4; ++nt) {
                    mma16816(acc[mt][nt], fAh[mt], fBh[nt]);
                    mma16816(acc[mt][nt], fAl[mt], fBh[nt]);
                    mma16816(acc[mt][nt], fAh[mt], fBl[nt]);
                }
        }
        // ---- drain: RN-add chunk partial into master, reset acc
#pragma unroll
        for (int mt = 0; mt < 2; ++mt)
#pragma unroll
            for (int nt = 0; nt < 4; ++nt)
#pragma unroll
                for (int q = 0; q < 4; ++q) {
                    mst[mt][nt][q] += acc[mt][nt][q];
                    acc[mt][nt][q] = 0.f;
                }
        __syncthreads();          // compute done before ch+2 staging overwrites
    }

    // ---- epilogue
    const int mrow0 = wm * 32 + (lane >> 2);
    const int ncol0 = (lane & 3) * 2;
#pragma unroll
    for (int mt = 0; mt < 2; ++mt)
#pragma unroll
        for (int half = 0; half < 2; ++half) {
            int m = mrow0 + mt * 16 + half * 8;
            int v = v0 + m;
            size_t rowbase = ((size_t)f * VV + v) * Cout;
#pragma unroll
            for (int nt = 0; nt < 4; ++nt) {
                int col = co0 + wn * 32 + nt * 8 + ncol0;
                size_t oi = rowbase + col;
                float r0 = mst[mt][nt][half * 2 + 0] + bias[col];
                float r1 = mst[mt][nt][half * 2 + 1] + bias[col + 1];
                if (residual) { r0 += residual[oi]; r1 += residual[oi + 1]; }
                if (do_gelu) {
                    r0 = 0.5f * r0 * (1.f + erff(r0 * 0.7071067811865475f));
                    r1 = 0.5f * r1 * (1.f + erff(r1 * 0.7071067811865475f));
                }
                if (yf) { yf[oi] = r0; yf[oi + 1] = r1; }
                if (yh) {
                    __half h0 = __float2half(r0);
                    __half h1 = __float2half(r1);
                    yh[oi] = h0; yh[oi + 1] = h1;
                    yl[oi]     = __float2half(r0 - __half2float(h0));
                    yl[oi + 1] = __float2half(r1 - __half2float(h1));
                }
            }
        }
}

// ---------------------------------------------------------------------------
// Attention over time (20 steps) per (b, voxel, head). Writes fp16 hi/lo.
// ---------------------------------------------------------------------------
__global__ void __launch_bounds__(128)
attn_kernel(const float* __restrict__ q, const float* __restrict__ k,
            const float* __restrict__ v,
            __half* __restrict__ oh, __half* __restrict__ ol)
{
    __shared__ float sm[4][2380];
    int wlocal = threadIdx.x >> 5;
    int lane   = threadIdx.x & 31;
    int wid    = blockIdx.x * 4 + wlocal;
    int h  = wid & 7;
    int vx = (wid >> 3) & 511;
    int b  = wid >> 12;

    float* qs = sm[wlocal];
    float* ks = qs + 660;
    float* vs = ks + 660;
    float* at = vs + 660;

    size_t base = (size_t)vx * EE + h * HEADD + lane;
#pragma unroll
    for (int s = 0; s < SS; ++s) {
        size_t gi = (size_t)(b * SS + s) * (VV * EE) + base;
        qs[s * 33 + lane] = q[gi];
        ks[s * 33 + lane] = k[gi];
        vs[s * 33 + lane] = v[gi];
    }
    __syncwarp();

    const float scale = 0.17677669529663687f;
    int tt = lane;
#pragma unroll 1
    for (int s = 0; s < SS; ++s) {
        float sc = -1e30f;
        if (tt < SS) {
            float a = 0.f;
#pragma unroll
            for (int d = 0; d < HEADD; ++d)
                a = fmaf(qs[s * 33 + d], ks[tt * 33 + d], a);
            sc = a * scale;
        }
        float m = sc;
#pragma unroll
        for (int off = 16; off > 0; off >>= 1)
            m = fmaxf(m, __shfl_xor_sync(0xffffffffu, m, off));
        float e = (tt < SS) ? expf(sc - m) : 0.f;
        float su = e;
#pragma unroll
        for (int off = 16; off > 0; off >>= 1)
            su += __shfl_xor_sync(0xffffffffu, su, off);
        if (tt < SS) at[s * SS + tt] = e / su;
    }
    __syncwarp();

#pragma unroll 1
    for (int s = 0; s < SS; ++s) {
        float a = 0.f;
#pragma unroll
        for (int t2 = 0; t2 < SS; ++t2)
            a = fmaf(at[s * SS + t2], vs[t2 * 33 + lane], a);
        size_t gi = (size_t)(b * SS + s) * (VV * EE) + base;
        __half hb = __float2half(a);
        oh[gi] = hb;
        ol[gi] = __float2half(a - __half2float(hb));
    }
}

// ---------------------------------------------------------------------------
// Final linear: [40960 x 256] @ [256 x 512] + bias
// ---------------------------------------------------------------------------
__global__ void __launch_bounds__(256)
linear_kernel(const float* __restrict__ A, const float* __restrict__ Bw,
              const float* __restrict__ bias, float* __restrict__ C)
{
    __shared__ float As[32 * 65];
    __shared__ float Bs[32 * 64];
    int t  = threadIdx.x;
    int tx = t & 15, ty = t >> 4;
    int m0 = blockIdx.x * 64, n0 = blockIdx.y * 64;
    float acc[4][4];
#pragma unroll
    for (int i = 0; i < 4; ++i)
#pragma unroll
        for (int j = 0; j < 4; ++j) acc[i][j] = 0.f;

    for (int kt = 0; kt < 8; ++kt) {
        for (int i = t; i < 2048; i += 256) {
            int r = i >> 5, kk = i & 31;
            As[kk * 65 + r] = A[(size_t)(m0 + r) * EE + kt * 32 + kk];
        }
        for (int i = t; i < 2048; i += 256) {
            int kk = i >> 6, c = i & 63;
            Bs[kk * 64 + c] = Bw[(size_t)(kt * 32 + kk) * NEE + n0 + c];
        }
        __syncthreads();
#pragma unroll
        for (int kk = 0; kk < 32; ++kk) {
            float a[4];
#pragma unroll
            for (int i = 0; i < 4; ++i) a[i] = As[kk * 65 + ty * 4 + i];
            float4 bvv = *(const float4*)&Bs[kk * 64 + tx * 4];
            float bvals[4] = {bvv.x, bvv.y, bvv.z, bvv.w};
#pragma unroll
            for (int i = 0; i < 4; ++i)
#pragma unroll
                for (int j = 0; j < 4; ++j)
                    acc[i][j] = fmaf(a[i], bvals[j], acc[i][j]);
        }
        __syncthreads();
    }
#pragma unroll
    for (int i = 0; i < 4; ++i)
#pragma unroll
        for (int j = 0; j < 4; ++j)
            C[(size_t)(m0 + ty * 4 + i) * NEE + n0 + tx * 4 + j] =
                acc[i][j] + bias[n0 + tx * 4 + j];
}

// ---------------------------------------------------------------------------
// Score transpose
// ---------------------------------------------------------------------------
__global__ void score_kernel(const float* __restrict__ logits, float* __restrict__ out,
                             int out_size)
{
    __shared__ float tile[32][33];
    int bp = blockIdx.z;
    int b = bp >> 2, p = bp & 3;
    int v0 = blockIdx.x * 32, c0 = blockIdx.y * 32;
    int f = b * SS + BPTT + p;
    int t = threadIdx.x;
    int ci = t & 31, vi = t >> 5;
#pragma unroll
    for (int r = 0; r < 32; r += 8)
        tile[vi + r][ci] = logits[((size_t)f * VV + v0 + vi + r) * NEE + c0 + ci];
    __syncthreads();
    int vv2 = t & 31, cc = t >> 5;
#pragma unroll
    for (int r = 0; r < 32; r += 8) {
        size_t oidx = (((size_t)(b * NEE + c0 + cc + r)) * PRED + p) * VV + v0 + vv2;
        if (oidx < (size_t)out_size) out[oidx] = tile[vv2][cc + r];
    }
}

// ---------------------------------------------------------------------------
// Loss + argmax
// ---------------------------------------------------------------------------
__global__ void loss_argmax_kernel(const float* __restrict__ logits,
                                   const int* __restrict__ ncode,
                                   float* __restrict__ rowloss,
                                   float* __restrict__ out, int write_code)
{
    int wid  = (int)((blockIdx.x * blockDim.x + threadIdx.x) >> 5);
    int lane = threadIdx.x & 31;
    if (wid >= NROWS) return;
    int v = wid & 511, p = (wid >> 9) & 3, b = wid >> 11;
    const float* lp = logits + ((size_t)(b * SS + BPTT + p) * VV + v) * NEE;

    float vals[16];
    float mx = -1e30f;
    int mi = 0;
#pragma unroll
    for (int i = 0; i < 16; ++i) {
        int c = lane + i * 32;
        float xv = lp[c];
        vals[i] = xv;
        if (xv > mx) { mx = xv; mi = c; }
    }
#pragma unroll
    for (int off = 16; off > 0; off >>= 1) {
        float om = __shfl_xor_sync(0xffffffffu, mx, off);
        int   oi = __shfl_xor_sync(0xffffffffu, mi, off);
        if (om > mx || (om == mx && oi < mi)) { mx = om; mi = oi; }
    }
    float se = 0.f;
#pragma unroll
    for (int i = 0; i < 16; ++i) se += expf(vals[i] - mx);
#pragma unroll
    for (int off = 16; off > 0; off >>= 1)
        se += __shfl_xor_sync(0xffffffffu, se, off);

    int tgt = ncode[wid];
    if (lane == (tgt & 31))
        rowloss[wid] = -(vals[tgt >> 5] - mx - logf(se));
    if (write_code && lane == 0)
        out[(size_t)SCORE_SIZE + 1 + wid] = (float)mi;
}

__global__ void loss_reduce_kernel(const float* __restrict__ rowloss,
                                   float* __restrict__ out, int loss_off)
{
    __shared__ float smr[256];
    int t = threadIdx.x;
    float a = 0.f;
    for (int i = t; i < NROWS; i += 256) a += rowloss[i];
    smr[t] = a;
    __syncthreads();
    for (int s = 128; s > 0; s >>= 1) {
        if (t < s) smr[t] += smr[t + s];
        __syncthreads();
    }
    if (t == 0) out[loss_off] = smr[0] * (1.f / (float)NROWS);
}

// ---------------------------------------------------------------------------
// Orchestration
// ---------------------------------------------------------------------------
extern "C" void kernel_launch(void* const* d_in, const int* in_sizes, int n_in,
                              void* d_out, int out_size)
{
    (void)in_sizes; (void)n_in;
    const int*   code   = (const int*)  d_in[0];
    const int*   ncode  = (const int*)  d_in[1];
    const float* emb    = (const float*)d_in[2];
    const float* pos    = (const float*)d_in[3];
    const float* ln1s   = (const float*)d_in[4];
    const float* ln1b   = (const float*)d_in[5];
    const float* ln2s   = (const float*)d_in[6];
    const float* ln2b   = (const float*)d_in[7];
    const float* wq     = (const float*)d_in[8];
    const float* bq     = (const float*)d_in[9];
    const float* wk     = (const float*)d_in[10];
    const float* bk     = (const float*)d_in[11];
    const float* wv     = (const float*)d_in[12];
    const float* bv     = (const float*)d_in[13];
    const float* wo     = (const float*)d_in[14];
    const float* bo     = (const float*)d_in[15];
    const float* w1     = (const float*)d_in[16];
    const float* b1     = (const float*)d_in[17];
    const float* w2     = (const float*)d_in[18];
    const float* b2     = (const float*)d_in[19];
    const float* lnfs   = (const float*)d_in[20];
    const float* lnfb   = (const float*)d_in[21];
    const float* decw   = (const float*)d_in[22];
    const float* decb   = (const float*)d_in[23];
    const float* declns = (const float*)d_in[24];
    const float* declnb = (const float*)d_in[25];
    const float* linw   = (const float*)d_in[26];
    const float* linb   = (const float*)d_in[27];
    float* out = (float*)d_out;

    float *px, *pq, *pk, *pv, *plog, *prl;
    __half *pah, *pal, *pbh, *pbl, *pwh, *pwl;
    cudaGetSymbolAddress((void**)&px,   g_x);
    cudaGetSymbolAddress((void**)&pq,   g_q);
    cudaGetSymbolAddress((void**)&pk,   g_k);
    cudaGetSymbolAddress((void**)&pv,   g_v);
    cudaGetSymbolAddress((void**)&plog, g_logits);
    cudaGetSymbolAddress((void**)&prl,  g_rowloss);
    cudaGetSymbolAddress((void**)&pah,  g_ah);
    cudaGetSymbolAddress((void**)&pal,  g_al);
    cudaGetSymbolAddress((void**)&pbh,  g_bh);
    cudaGetSymbolAddress((void**)&pbl,  g_bl);
    cudaGetSymbolAddress((void**)&pwh,  g_wth);
    cudaGetSymbolAddress((void**)&pwl,  g_wtl);

    cudaFuncSetAttribute(conv3d_mma_kernel,
                         cudaFuncAttributeMaxDynamicSharedMemorySize,
                         TC_SMEM_BYTES);

    const int ROWS = FF * VV;
    const int LN_BLOCKS = (ROWS * 32) / 256;
    const size_t WEE = 27 * 256 * 256;
    const size_t WEH = 27 * 256 * 512;

    // ---- convert + transpose all conv weights to fp16 hi/lo ----
    auto wcv = [&](const float* w, size_t off, int Cin, int Cout) {
        size_t n = (size_t)27 * Cin * Cout;
        wconv_kernel<<<(unsigned)((n + 255) / 256), 256>>>(w, pwh + off, pwl + off, Cin, Cout);
    };
    for (int i = 0; i < 4; ++i) {
        size_t base = (size_t)i * WT_LAYER;
        wcv(wq + i * WEE, base + 0 * WEE27, 256, 256);
        wcv(wk + i * WEE, base + 1 * WEE27, 256, 256);
        wcv(wv + i * WEE, base + 2 * WEE27, 256, 256);
        wcv(wo + i * WEE, base + 3 * WEE27, 256, 256);
        wcv(w1 + i * WEH, base + 4 * WEE27, 256, 512);
        wcv(w2 + i * WEH, base + 4 * WEE27 + WEH27, 512, 256);
    }
    const size_t offdec = 4 * WT_LAYER;
    wcv(decw, offdec, 256, 256);

    embed_kernel<<<(int)((FVE + 255) / 256), 256>>>(code, emb, pos, px);

    dim3 cgE(FF, 4, 4);   // Cout=256
    dim3 cgH(FF, 8, 4);   // Cout=512
    for (int i = 0; i < 4; ++i) {
        size_t base = (size_t)i * WT_LAYER;
        ln_kernel<<<LN_BLOCKS, 256>>>(px, nullptr, pah, pal,
                                      ln1s + i * EE, ln1b + i * EE, ROWS);
        conv3d_mma_kernel<<<cgE, 256, TC_SMEM_BYTES>>>(pah, pal,
            pwh + base + 0 * WEE27, pwl + base + 0 * WEE27,
            bq + i * EE, nullptr, pq, nullptr, nullptr, 256, 256, 0);
        conv3d_mma_kernel<<<cgE, 256, TC_SMEM_BYTES>>>(pah, pal,
            pwh + base + 1 * WEE27, pwl + base + 1 * WEE27,
            bk + i * EE, nullptr, pk, nullptr, nullptr, 256, 256, 0);
        conv3d_mma_kernel<<<cgE, 256, TC_SMEM_BYTES>>>(pah, pal,
            pwh + base + 2 * WEE27, pwl + base + 2 * WEE27,
            bv + i * EE, nullptr, pv, nullptr, nullptr, 256, 256, 0);
        attn_kernel<<<4096, 128>>>(pq, pk, pv, pah, pal);
        conv3d_mma_kernel<<<cgE, 256, TC_SMEM_BYTES>>>(pah, pal,
            pwh + base + 3 * WEE27, pwl + base + 3 * WEE27,
            bo + i * EE, px, px, nullptr, nullptr, 256, 256, 0);
        ln_kernel<<<LN_BLOCKS, 256>>>(px, nullptr, pah, pal,
                                      ln2s + i * EE, ln2b + i * EE, ROWS);
        conv3d_mma_kernel<<<cgH, 256, TC_SMEM_BYTES>>>(pah, pal,
            pwh + base + 4 * WEE27, pwl + base + 4 * WEE27,
            b1 + i * HIDD, nullptr, nullptr, pbh, pbl, 256, 512, 1);
        conv3d_mma_kernel<<<cgE, 256, TC_SMEM_BYTES>>>(pbh, pbl,
            pwh + base + 4 * WEE27 + WEH27, pwl + base + 4 * WEE27 + WEH27,
            b2 + i * EE, px, px, nullptr, nullptr, 512, 256, 0);
    }

    ln_kernel<<<LN_BLOCKS, 256>>>(px, nullptr, pah, pal, lnfs, lnfb, ROWS);
    conv3d_mma_kernel<<<cgE, 256, TC_SMEM_BYTES>>>(pah, pal,
        pwh + offdec, pwl + offdec, decb, nullptr, pq, nullptr, nullptr, 256, 256, 1);
    ln_kernel<<<LN_BLOCKS, 256>>>(pq, pk, nullptr, nullptr, declns, declnb, ROWS);
    linear_kernel<<<dim3(ROWS / 64, NEE / 64), 256>>>(pk, linw, linb, plog);

    if (out_size >= SCORE_SIZE) {
        dim3 sg(16, 16, 16);
        score_kernel<<<sg, 256>>>(plog, out, out_size);
    }
    int write_code = (out_size >= SCORE_SIZE + 1 + NROWS) ? 1 : 0;
    loss_argmax_kernel<<<(NROWS * 32) / 256, 256>>>(plog, ncode, prl, out, write_code);

    int loss_off = -1;
    if (out_size == 1) loss_off = 0;
    else if (out_size > SCORE_SIZE) loss_off = SCORE_SIZE;
    if (loss_off >= 0)
        loss_reduce_kernel<<<1, 256>>>(prl, out, loss_off);
}

// round 16
// speedup vs baseline: 1.2194x; 1.2194x over previous
#include <cuda_runtime.h>
#include <cuda_fp16.h>
#include <math.h>

// ---------------------------------------------------------------------------
// Problem constants
// ---------------------------------------------------------------------------
#define BB    4
#define BPTT  16
#define PRED  4
#define SS    20
#define VV    512
#define EE    256
#define NHH   8
#define HEADD 32
#define HIDD  512
#define NEE   512
#define FF    80

#define FVE   ((size_t)FF * VV * EE)
#define FVH   ((size_t)FF * VV * HIDD)
#define SCORE_SIZE (BB * NEE * PRED * VV)
#define NROWS (BB * PRED * VV)

#define WEE27 1769472ull                 // 27*256*256
#define WEH27 3538944ull                 // 27*256*512
#define WT_LAYER (4ull*WEE27 + 2ull*WEH27)
#define WT_TOTAL (4ull*WT_LAYER + WEE27)

// ---------------------------------------------------------------------------
// Scratch (allocation-free: __device__ globals)
// ---------------------------------------------------------------------------
__device__ float g_x[FVE];
__device__ float g_q[FVE];
__device__ float g_k[FVE];
__device__ float g_v[FVE];
__device__ float g_logits[FVH];
__device__ float g_rowloss[NROWS];
__device__ __half g_ah[FVE];
__device__ __half g_al[FVE];
__device__ __half g_bh[FVH];
__device__ __half g_bl[FVH];
__device__ __half g_wth[WT_TOTAL];
__device__ __half g_wtl[WT_TOTAL];

// ---------------------------------------------------------------------------
// PTX helpers (baseline sm_103-compatible: cp.async, ldmatrix, mma.sync)
// ---------------------------------------------------------------------------
__device__ __forceinline__ unsigned smem_u32(const void* p) {
    unsigned a;
    asm("{ .reg .u64 t; cvta.to.shared.u64 t, %1; cvt.u32.u64 %0, t; }"
        : "=r"(a) : "l"(p));
    return a;
}
__device__ __forceinline__ void cp_async16z(unsigned dst, const void* src, int ssz) {
    asm volatile("cp.async.cg.shared.global [%0], [%1], 16, %2;"
                 :: "r"(dst), "l"(src), "r"(ssz) : "memory");
}
__device__ __forceinline__ void ldsm4(unsigned* r, unsigned addr) {
    asm volatile("ldmatrix.sync.aligned.m8n8.x4.shared.b16 {%0,%1,%2,%3}, [%4];"
                 : "=r"(r[0]), "=r"(r[1]), "=r"(r[2]), "=r"(r[3]) : "r"(addr));
}
__device__ __forceinline__ void mma16816(float* d, const unsigned* a, const unsigned* b) {
    asm volatile(
        "mma.sync.aligned.m16n8k16.row.col.f32.f16.f16.f32 "
        "{%0,%1,%2,%3}, {%4,%5,%6,%7}, {%8,%9}, {%0,%1,%2,%3};"
        : "+f"(d[0]), "+f"(d[1]), "+f"(d[2]), "+f"(d[3])
        : "r"(a[0]), "r"(a[1]), "r"(a[2]), "r"(a[3]), "r"(b[0]), "r"(b[1]));
}

// ---------------------------------------------------------------------------
// Weight transpose + fp16 split:  w[27][Cin][Cout] f32 -> wt[27][Cout][Cin] hi/lo
// ---------------------------------------------------------------------------
__global__ void wconv_kernel(const float* __restrict__ w,
                             __half* __restrict__ th,
                             __half* __restrict__ tl,
                             int Cin, int Cout)
{
    size_t n = (size_t)27 * Cin * Cout;
    size_t i = (size_t)blockIdx.x * 256 + threadIdx.x;
    if (i >= n) return;
    int pc = Cin * Cout;
    int o = (int)(i / pc);
    int r = (int)(i - (size_t)o * pc);
    int co = r / Cin, ci = r - co * Cin;
    float x = w[((size_t)o * Cin + ci) * Cout + co];
    __half h = __float2half(x);
    th[i] = h;
    tl[i] = __float2half(x - __half2float(h));
}

// ---------------------------------------------------------------------------
// Embedding
// ---------------------------------------------------------------------------
__global__ void embed_kernel(const int* __restrict__ code,
                             const float* __restrict__ emb,
                             const float* __restrict__ pos,
                             float* __restrict__ x)
{
    size_t idx = (size_t)blockIdx.x * blockDim.x + threadIdx.x;
    if (idx >= FVE) return;
    int e = (int)(idx & 255);
    int v = (int)((idx >> 8) & 511);
    int f = (int)(idx >> 17);
    int b = f / SS, s = f % SS;
    int tok = (s < BPTT) ? code[((b * BPTT + s) << 9) + v] : NEE;
    x[idx] = emb[tok * EE + e] + pos[s * EE + e];
}

// ---------------------------------------------------------------------------
// LayerNorm; writes f32 and/or fp16 hi/lo pair
// ---------------------------------------------------------------------------
__global__ void ln_kernel(const float* __restrict__ in,
                          float* __restrict__ outF,
                          __half* __restrict__ outH,
                          __half* __restrict__ outL,
                          const float* __restrict__ sc, const float* __restrict__ bi,
                          int rows)
{
    int wid  = (int)((blockIdx.x * blockDim.x + threadIdx.x) >> 5);
    int lane = threadIdx.x & 31;
    if (wid >= rows) return;
    const float* p = in + (size_t)wid * EE;
    float v8[8];
    float s = 0.f, sq = 0.f;
#pragma unroll
    for (int i = 0; i < 8; ++i) {
        float xv = p[lane + i * 32];
        v8[i] = xv; s += xv; sq = fmaf(xv, xv, sq);
    }
#pragma unroll
    for (int off = 16; off > 0; off >>= 1) {
        s  += __shfl_xor_sync(0xffffffffu, s, off);
        sq += __shfl_xor_sync(0xffffffffu, sq, off);
    }
    float m   = s * (1.f / 256.f);
    float var = sq * (1.f / 256.f) - m * m;
    if (var < 0.f) var = 0.f;
    float inv = rsqrtf(var + 1e-5f);
#pragma unroll
    for (int i = 0; i < 8; ++i) {
        int e = lane + i * 32;
        float r = (v8[i] - m) * inv * sc[e] + bi[e];
        size_t oi = (size_t)wid * EE + e;
        if (outF) outF[oi] = r;
        if (outH) {
            __half h = __float2half(r);
            outH[oi] = h;
            outL[oi] = __float2half(r - __half2float(h));
        }
    }
}

// ---------------------------------------------------------------------------
// Tensor-core (mma.sync fp16) 3D conv, 3x3x3 SAME, fp16x3 split precision,
// per-chunk RN accumulator drain (bounds mma RZ bias), 2-STAGE cp.async
// PIPELINE at 2 CTAs/SM: __launch_bounds__(256,2) caps regs at 128 so two
// CTAs co-reside (221KB smem total) -- inter-CTA overlap AND intra-CTA
// pipelining (chunk k+1 stages under chunk k's compute, wait_group 1).
//   CTA: 256 thr (8 warps), tile M=128 x N=64; warp tile 32x32.
//   K loop = 27 taps x Cin/64 chunks.
// ---------------------------------------------------------------------------
#define APAD 144                           // bytes per smem row (72 halves)
#define AH_OFF 0
#define AL_OFF (128 * APAD)                // 18432
#define BH_OFF (2 * 128 * APAD)            // 36864
#define BL_OFF (BH_OFF + 64 * APAD)        // 46080
#define STG_STRIDE (BL_OFF + 64 * APAD)    // 55296
#define TC_SMEM_BYTES (2 * STG_STRIDE)     // 110592

__global__ void __launch_bounds__(256, 2)
conv3d_mma_kernel(const __half* __restrict__ xh,
                  const __half* __restrict__ xl,
                  const __half* __restrict__ wth,
                  const __half* __restrict__ wtl,
                  const float* __restrict__ bias, const float* __restrict__ residual,
                  float* __restrict__ yf,
                  __half* __restrict__ yh, __half* __restrict__ yl,
                  int Cin, int Cout, int do_gelu)
{
    extern __shared__ char smem[];
    unsigned sb = smem_u32(smem);
    const int t = threadIdx.x, w = t >> 5, lane = t & 31;
    const int wm = w & 3, wn = w >> 2;      // warp covers rows wm*32, cols wn*32
    const int f = blockIdx.x, co0 = blockIdx.y * 64, v0 = blockIdx.z * 128;

    // A staging: thread t -> tile row t/2, 32-half part t&1
    const int arow = t >> 1, apart = t & 1;
    const int av = v0 + arow, vz = av >> 6, vy = (av >> 3) & 7, vx = av & 7;
    // B staging: thread t -> cout row t/4, quads (t&3)*2..+1
    const int brow = t >> 2, bq0 = (t & 3) * 2;

    float acc[2][4][4], mst[2][4][4];
#pragma unroll
    for (int mt = 0; mt < 2; ++mt)
#pragma unroll
        for (int nt = 0; nt < 4; ++nt)
#pragma unroll
            for (int q = 0; q < 4; ++q) { acc[mt][nt][q] = 0.f; mst[mt][nt][q] = 0.f; }

    // ldmatrix lane base offsets (relative to stage base)
    const int rA = ((lane >> 3) & 1) * 8 + (lane & 7);
    const int cA = (lane >> 4) * 16;
    unsigned oAh[2], oAl[2];
#pragma unroll
    for (int mt = 0; mt < 2; ++mt) {
        unsigned off = (unsigned)(wm * 32 + mt * 16 + rA) * APAD + cA;
        oAh[mt] = AH_OFF + off;
        oAl[mt] = AL_OFF + off;
    }
    const int rB = ((lane >> 4) & 1) * 8 + (lane & 7);
    const int cB = ((lane >> 3) & 1) * 16;
    unsigned oBh[2], oBl[2];
#pragma unroll
    for (int nt2 = 0; nt2 < 2; ++nt2) {
        unsigned off = (unsigned)(wn * 32 + nt2 * 16 + rB) * APAD + cB;
        oBh[nt2] = BH_OFF + off;
        oBl[nt2] = BL_OFF + off;
    }

    const int ncc = Cin >> 6;
    const int nchunks = 27 * ncc;

    // staging helper: stage chunk ch into buffer base sbase; one commit_group
    auto stage_chunk = [&](int ch, unsigned sbase) {
        int o = ch / ncc, c = ch - o * ncc;
        int dz = o / 9 - 1, dy = (o % 9) / 3 - 1, dx = o % 3 - 1;
        int zz = vz + dz, yy = vy + dy, xx = vx + dx;
        int ok = ((unsigned)zz < 8u) && ((unsigned)yy < 8u) && ((unsigned)xx < 8u);
        size_t abase = ((size_t)f * VV + (size_t)(zz * 64 + yy * 8 + xx)) * Cin
                       + (size_t)c * 64 + apart * 32;
        const __half* sah = ok ? (xh + abase) : xh;
        const __half* sal = ok ? (xl + abase) : xl;
        int ssz = ok ? 16 : 0;
        unsigned dah = sbase + AH_OFF + (unsigned)arow * APAD + apart * 64;
        unsigned dal = sbase + AL_OFF + (unsigned)arow * APAD + apart * 64;
#pragma unroll
        for (int i = 0; i < 4; ++i) {
            cp_async16z(dah + i * 16, sah + i * 8, ssz);
            cp_async16z(dal + i * 16, sal + i * 8, ssz);
        }
        size_t bbase = ((size_t)o * Cout + (size_t)(co0 + brow)) * Cin + (size_t)c * 64;
        unsigned dbh = sbase + BH_OFF + (unsigned)brow * APAD;
        unsigned dbl = sbase + BL_OFF + (unsigned)brow * APAD;
#pragma unroll
        for (int q2 = 0; q2 < 2; ++q2) {
            int i = bq0 + q2;
            cp_async16z(dbh + i * 16, wth + bbase + i * 8, 16);
            cp_async16z(dbl + i * 16, wtl + bbase + i * 8, 16);
        }
        asm volatile("cp.async.commit_group;" ::: "memory");
    };

    // ---- prologue: stage chunk 0
    stage_chunk(0, sb);

    for (int ch = 0; ch < nchunks; ++ch) {
        if (ch + 1 < nchunks) {
            stage_chunk(ch + 1, sb + (unsigned)((ch + 1) & 1) * STG_STRIDE);
            asm volatile("cp.async.wait_group 1;" ::: "memory");
        } else {
            asm volatile("cp.async.wait_group 0;" ::: "memory");
        }
        __syncthreads();          // chunk ch data visible to all threads

        unsigned sbase = sb + (unsigned)(ch & 1) * STG_STRIDE;

        // ---- compute: 4 k16 steps x (2 mt x 4 nt) x 3 terms
#pragma unroll
        for (int ks = 0; ks < 4; ++ks) {
            unsigned kb = (unsigned)ks * 32;
            unsigned fAh[2][4], fAl[2][4], fBh[4][2], fBl[4][2];
#pragma unroll
            for (int mt = 0; mt < 2; ++mt) {
                ldsm4(fAh[mt], sbase + oAh[mt] + kb);
                ldsm4(fAl[mt], sbase + oAl[mt] + kb);
            }
#pragma unroll
            for (int nt2 = 0; nt2 < 2; ++nt2) {
                unsigned r4[4];
                ldsm4(r4, sbase + oBh[nt2] + kb);
                fBh[nt2 * 2][0] = r4[0]; fBh[nt2 * 2][1] = r4[1];
                fBh[nt2 * 2 + 1][0] = r4[2]; fBh[nt2 * 2 + 1][1] = r4[3];
                ldsm4(r4, sbase + oBl[nt2] + kb);
                fBl[nt2 * 2][0] = r4[0]; fBl[nt2 * 2][1] = r4[1];
                fBl[nt2 * 2 + 1][0] = r4[2]; fBl[nt2 * 2 + 1][1] = r4[3];
            }
#pragma unroll
            for (int mt = 0; mt < 2; ++mt)
#pragma unroll
                for (int nt = 0; nt < 4; ++nt) {
                    mma16816(acc[mt][nt], fAh[mt], fBh[nt]);
                    mma16816(acc[mt][nt], fAl[mt], fBh[nt]);
                    mma16816(acc[mt][nt], fAh[mt], fBl[nt]);
                }
        }
        // ---- drain: RN-add chunk partial into master, reset acc
#pragma unroll
        for (int mt = 0; mt < 2; ++mt)
#pragma unroll
            for (int nt = 0; nt < 4; ++nt)
#pragma unroll
                for (int q = 0; q < 4; ++q) {
                    mst[mt][nt][q] += acc[mt][nt][q];
                    acc[mt][nt][q] = 0.f;
                }
        __syncthreads();          // compute done before ch+2 staging overwrites
    }

    // ---- epilogue
    const int mrow0 = wm * 32 + (lane >> 2);
    const int ncol0 = (lane & 3) * 2;
#pragma unroll
    for (int mt = 0; mt < 2; ++mt)
#pragma unroll
        for (int half = 0; half < 2; ++half) {
            int m = mrow0 + mt * 16 + half * 8;
            int v = v0 + m;
            size_t rowbase = ((size_t)f * VV + v) * Cout;
#pragma unroll
            for (int nt = 0; nt < 4; ++nt) {
                int col = co0 + wn * 32 + nt * 8 + ncol0;
                size_t oi = rowbase + col;
                float r0 = mst[mt][nt][half * 2 + 0] + bias[col];
                float r1 = mst[mt][nt][half * 2 + 1] + bias[col + 1];
                if (residual) { r0 += residual[oi]; r1 += residual[oi + 1]; }
                if (do_gelu) {
                    r0 = 0.5f * r0 * (1.f + erff(r0 * 0.7071067811865475f));
                    r1 = 0.5f * r1 * (1.f + erff(r1 * 0.7071067811865475f));
                }
                if (yf) { yf[oi] = r0; yf[oi + 1] = r1; }
                if (yh) {
                    __half h0 = __float2half(r0);
                    __half h1 = __float2half(r1);
                    yh[oi] = h0; yh[oi + 1] = h1;
                    yl[oi]     = __float2half(r0 - __half2float(h0));
                    yl[oi + 1] = __float2half(r1 - __half2float(h1));
                }
            }
        }
}

// ---------------------------------------------------------------------------
// Attention over time (20 steps) per (b, voxel, head). Writes fp16 hi/lo.
// ---------------------------------------------------------------------------
__global__ void __launch_bounds__(128)
attn_kernel(const float* __restrict__ q, const float* __restrict__ k,
            const float* __restrict__ v,
            __half* __restrict__ oh, __half* __restrict__ ol)
{
    __shared__ float sm[4][2380];
    int wlocal = threadIdx.x >> 5;
    int lane   = threadIdx.x & 31;
    int wid    = blockIdx.x * 4 + wlocal;
    int h  = wid & 7;
    int vx = (wid >> 3) & 511;
    int b  = wid >> 12;

    float* qs = sm[wlocal];
    float* ks = qs + 660;
    float* vs = ks + 660;
    float* at = vs + 660;

    size_t base = (size_t)vx * EE + h * HEADD + lane;
#pragma unroll
    for (int s = 0; s < SS; ++s) {
        size_t gi = (size_t)(b * SS + s) * (VV * EE) + base;
        qs[s * 33 + lane] = q[gi];
        ks[s * 33 + lane] = k[gi];
        vs[s * 33 + lane] = v[gi];
    }
    __syncwarp();

    const float scale = 0.17677669529663687f;
    int tt = lane;
#pragma unroll 1
    for (int s = 0; s < SS; ++s) {
        float sc = -1e30f;
        if (tt < SS) {
            float a = 0.f;
#pragma unroll
            for (int d = 0; d < HEADD; ++d)
                a = fmaf(qs[s * 33 + d], ks[tt * 33 + d], a);
            sc = a * scale;
        }
        float m = sc;
#pragma unroll
        for (int off = 16; off > 0; off >>= 1)
            m = fmaxf(m, __shfl_xor_sync(0xffffffffu, m, off));
        float e = (tt < SS) ? expf(sc - m) : 0.f;
        float su = e;
#pragma unroll
        for (int off = 16; off > 0; off >>= 1)
            su += __shfl_xor_sync(0xffffffffu, su, off);
        if (tt < SS) at[s * SS + tt] = e / su;
    }
    __syncwarp();

#pragma unroll 1
    for (int s = 0; s < SS; ++s) {
        float a = 0.f;
#pragma unroll
        for (int t2 = 0; t2 < SS; ++t2)
            a = fmaf(at[s * SS + t2], vs[t2 * 33 + lane], a);
        size_t gi = (size_t)(b * SS + s) * (VV * EE) + base;
        __half hb = __float2half(a);
        oh[gi] = hb;
        ol[gi] = __float2half(a - __half2float(hb));
    }
}

// ---------------------------------------------------------------------------
// Final linear: [40960 x 256] @ [256 x 512] + bias
// ---------------------------------------------------------------------------
__global__ void __launch_bounds__(256)
linear_kernel(const float* __restrict__ A, const float* __restrict__ Bw,
              const float* __restrict__ bias, float* __restrict__ C)
{
    __shared__ float As[32 * 65];
    __shared__ float Bs[32 * 64];
    int t  = threadIdx.x;
    int tx = t & 15, ty = t >> 4;
    int m0 = blockIdx.x * 64, n0 = blockIdx.y * 64;
    float acc[4][4];
#pragma unroll
    for (int i = 0; i < 4; ++i)
#pragma unroll
        for (int j = 0; j < 4; ++j) acc[i][j] = 0.f;

    for (int kt = 0; kt < 8; ++kt) {
        for (int i = t; i < 2048; i += 256) {
            int r = i >> 5, kk = i & 31;
            As[kk * 65 + r] = A[(size_t)(m0 + r) * EE + kt * 32 + kk];
        }
        for (int i = t; i < 2048; i += 256) {
            int kk = i >> 6, c = i & 63;
            Bs[kk * 64 + c] = Bw[(size_t)(kt * 32 + kk) * NEE + n0 + c];
        }
        __syncthreads();
#pragma unroll
        for (int kk = 0; kk < 32; ++kk) {
            float a[4];
#pragma unroll
            for (int i = 0; i < 4; ++i) a[i] = As[kk * 65 + ty * 4 + i];
            float4 bvv = *(const float4*)&Bs[kk * 64 + tx * 4];
            float bvals[4] = {bvv.x, bvv.y, bvv.z, bvv.w};
#pragma unroll
            for (int i = 0; i < 4; ++i)
#pragma unroll
                for (int j = 0; j < 4; ++j)
                    acc[i][j] = fmaf(a[i], bvals[j], acc[i][j]);
        }
        __syncthreads();
    }
#pragma unroll
    for (int i = 0; i < 4; ++i)
#pragma unroll
        for (int j = 0; j < 4; ++j)
            C[(size_t)(m0 + ty * 4 + i) * NEE + n0 + tx * 4 + j] =
                acc[i][j] + bias[n0 + tx * 4 + j];
}

// ---------------------------------------------------------------------------
// Score transpose
// ---------------------------------------------------------------------------
__global__ void score_kernel(const float* __restrict__ logits, float* __restrict__ out,
                             int out_size)
{
    __shared__ float tile[32][33];
    int bp = blockIdx.z;
    int b = bp >> 2, p = bp & 3;
    int v0 = blockIdx.x * 32, c0 = blockIdx.y * 32;
    int f = b * SS + BPTT + p;
    int t = threadIdx.x;
    int ci = t & 31, vi = t >> 5;
#pragma unroll
    for (int r = 0; r < 32; r += 8)
        tile[vi + r][ci] = logits[((size_t)f * VV + v0 + vi + r) * NEE + c0 + ci];
    __syncthreads();
    int vv2 = t & 31, cc = t >> 5;
#pragma unroll
    for (int r = 0; r < 32; r += 8) {
        size_t oidx = (((size_t)(b * NEE + c0 + cc + r)) * PRED + p) * VV + v0 + vv2;
        if (oidx < (size_t)out_size) out[oidx] = tile[vv2][cc + r];
    }
}

// ---------------------------------------------------------------------------
// Loss + argmax
// ---------------------------------------------------------------------------
__global__ void loss_argmax_kernel(const float* __restrict__ logits,
                                   const int* __restrict__ ncode,
                                   float* __restrict__ rowloss,
                                   float* __restrict__ out, int write_code)
{
    int wid  = (int)((blockIdx.x * blockDim.x + threadIdx.x) >> 5);
    int lane = threadIdx.x & 31;
    if (wid >= NROWS) return;
    int v = wid & 511, p = (wid >> 9) & 3, b = wid >> 11;
    const float* lp = logits + ((size_t)(b * SS + BPTT + p) * VV + v) * NEE;

    float vals[16];
    float mx = -1e30f;
    int mi = 0;
#pragma unroll
    for (int i = 0; i < 16; ++i) {
        int c = lane + i * 32;
        float xv = lp[c];
        vals[i] = xv;
        if (xv > mx) { mx = xv; mi = c; }
    }
#pragma unroll
    for (int off = 16; off > 0; off >>= 1) {
        float om = __shfl_xor_sync(0xffffffffu, mx, off);
        int   oi = __shfl_xor_sync(0xffffffffu, mi, off);
        if (om > mx || (om == mx && oi < mi)) { mx = om; mi = oi; }
    }
    float se = 0.f;
#pragma unroll
    for (int i = 0; i < 16; ++i) se += expf(vals[i] - mx);
#pragma unroll
    for (int off = 16; off > 0; off >>= 1)
        se += __shfl_xor_sync(0xffffffffu, se, off);

    int tgt = ncode[wid];
    if (lane == (tgt & 31))
        rowloss[wid] = -(vals[tgt >> 5] - mx - logf(se));
    if (write_code && lane == 0)
        out[(size_t)SCORE_SIZE + 1 + wid] = (float)mi;
}

__global__ void loss_reduce_kernel(const float* __restrict__ rowloss,
                                   float* __restrict__ out, int loss_off)
{
    __shared__ float smr[256];
    int t = threadIdx.x;
    float a = 0.f;
    for (int i = t; i < NROWS; i += 256) a += rowloss[i];
    smr[t] = a;
    __syncthreads();
    for (int s = 128; s > 0; s >>= 1) {
        if (t < s) smr[t] += smr[t + s];
        __syncthreads();
    }
    if (t == 0) out[loss_off] = smr[0] * (1.f / (float)NROWS);
}

// ---------------------------------------------------------------------------
// Orchestration
// ---------------------------------------------------------------------------
extern "C" void kernel_launch(void* const* d_in, const int* in_sizes, int n_in,
                              void* d_out, int out_size)
{
    (void)in_sizes; (void)n_in;
    const int*   code   = (const int*)  d_in[0];
    const int*   ncode  = (const int*)  d_in[1];
    const float* emb    = (const float*)d_in[2];
    const float* pos    = (const float*)d_in[3];
    const float* ln1s   = (const float*)d_in[4];
    const float* ln1b   = (const float*)d_in[5];
    const float* ln2s   = (const float*)d_in[6];
    const float* ln2b   = (const float*)d_in[7];
    const float* wq     = (const float*)d_in[8];
    const float* bq     = (const float*)d_in[9];
    const float* wk     = (const float*)d_in[10];
    const float* bk     = (const float*)d_in[11];
    const float* wv     = (const float*)d_in[12];
    const float* bv     = (const float*)d_in[13];
    const float* wo     = (const float*)d_in[14];
    const float* bo     = (const float*)d_in[15];
    const float* w1     = (const float*)d_in[16];
    const float* b1     = (const float*)d_in[17];
    const float* w2     = (const float*)d_in[18];
    const float* b2     = (const float*)d_in[19];
    const float* lnfs   = (const float*)d_in[20];
    const float* lnfb   = (const float*)d_in[21];
    const float* decw   = (const float*)d_in[22];
    const float* decb   = (const float*)d_in[23];
    const float* declns = (const float*)d_in[24];
    const float* declnb = (const float*)d_in[25];
    const float* linw   = (const float*)d_in[26];
    const float* linb   = (const float*)d_in[27];
    float* out = (float*)d_out;

    float *px, *pq, *pk, *pv, *plog, *prl;
    __half *pah, *pal, *pbh, *pbl, *pwh, *pwl;
    cudaGetSymbolAddress((void**)&px,   g_x);
    cudaGetSymbolAddress((void**)&pq,   g_q);
    cudaGetSymbolAddress((void**)&pk,   g_k);
    cudaGetSymbolAddress((void**)&pv,   g_v);
    cudaGetSymbolAddress((void**)&plog, g_logits);
    cudaGetSymbolAddress((void**)&prl,  g_rowloss);
    cudaGetSymbolAddress((void**)&pah,  g_ah);
    cudaGetSymbolAddress((void**)&pal,  g_al);
    cudaGetSymbolAddress((void**)&pbh,  g_bh);
    cudaGetSymbolAddress((void**)&pbl,  g_bl);
    cudaGetSymbolAddress((void**)&pwh,  g_wth);
    cudaGetSymbolAddress((void**)&pwl,  g_wtl);

    cudaFuncSetAttribute(conv3d_mma_kernel,
                         cudaFuncAttributeMaxDynamicSharedMemorySize,
                         TC_SMEM_BYTES);

    const int ROWS = FF * VV;
    const int LN_BLOCKS = (ROWS * 32) / 256;
    const size_t WEE = 27 * 256 * 256;
    const size_t WEH = 27 * 256 * 512;

    // ---- convert + transpose all conv weights to fp16 hi/lo ----
    auto wcv = [&](const float* w, size_t off, int Cin, int Cout) {
        size_t n = (size_t)27 * Cin * Cout;
        wconv_kernel<<<(unsigned)((n + 255) / 256), 256>>>(w, pwh + off, pwl + off, Cin, Cout);
    };
    for (int i = 0; i < 4; ++i) {
        size_t base = (size_t)i * WT_LAYER;
        wcv(wq + i * WEE, base + 0 * WEE27, 256, 256);
        wcv(wk + i * WEE, base + 1 * WEE27, 256, 256);
        wcv(wv + i * WEE, base + 2 * WEE27, 256, 256);
        wcv(wo + i * WEE, base + 3 * WEE27, 256, 256);
        wcv(w1 + i * WEH, base + 4 * WEE27, 256, 512);
        wcv(w2 + i * WEH, base + 4 * WEE27 + WEH27, 512, 256);
    }
    const size_t offdec = 4 * WT_LAYER;
    wcv(decw, offdec, 256, 256);

    embed_kernel<<<(int)((FVE + 255) / 256), 256>>>(code, emb, pos, px);

    dim3 cgE(FF, 4, 4);   // Cout=256
    dim3 cgH(FF, 8, 4);   // Cout=512
    for (int i = 0; i < 4; ++i) {
        size_t base = (size_t)i * WT_LAYER;
        ln_kernel<<<LN_BLOCKS, 256>>>(px, nullptr, pah, pal,
                                      ln1s + i * EE, ln1b + i * EE, ROWS);
        conv3d_mma_kernel<<<cgE, 256, TC_SMEM_BYTES>>>(pah, pal,
            pwh + base + 0 * WEE27, pwl + base + 0 * WEE27,
            bq + i * EE, nullptr, pq, nullptr, nullptr, 256, 256, 0);
        conv3d_mma_kernel<<<cgE, 256, TC_SMEM_BYTES>>>(pah, pal,
            pwh + base + 1 * WEE27, pwl + base + 1 * WEE27,
            bk + i * EE, nullptr, pk, nullptr, nullptr, 256, 256, 0);
        conv3d_mma_kernel<<<cgE, 256, TC_SMEM_BYTES>>>(pah, pal,
            pwh + base + 2 * WEE27, pwl + base + 2 * WEE27,
            bv + i * EE, nullptr, pv, nullptr, nullptr, 256, 256, 0);
        attn_kernel<<<4096, 128>>>(pq, pk, pv, pah, pal);
        conv3d_mma_kernel<<<cgE, 256, TC_SMEM_BYTES>>>(pah, pal,
            pwh + base + 3 * WEE27, pwl + base + 3 * WEE27,
            bo + i * EE, px, px, nullptr, nullptr, 256, 256, 0);
        ln_kernel<<<LN_BLOCKS, 256>>>(px, nullptr, pah, pal,
                                      ln2s + i * EE, ln2b + i * EE, ROWS);
        conv3d_mma_kernel<<<cgH, 256, TC_SMEM_BYTES>>>(pah, pal,
            pwh + base + 4 * WEE27, pwl + base + 4 * WEE27,
            b1 + i * HIDD, nullptr, nullptr, pbh, pbl, 256, 512, 1);
        conv3d_mma_kernel<<<cgE, 256, TC_SMEM_BYTES>>>(pbh, pbl,
            pwh + base + 4 * WEE27 + WEH27, pwl + base + 4 * WEE27 + WEH27,
            b2 + i * EE, px, px, nullptr, nullptr, 512, 256, 0);
    }

    ln_kernel<<<LN_BLOCKS, 256>>>(px, nullptr, pah, pal, lnfs, lnfb, ROWS);
    conv3d_mma_kernel<<<cgE, 256, TC_SMEM_BYTES>>>(pah, pal,
        pwh + offdec, pwl + offdec, decb, nullptr, pq, nullptr, nullptr, 256, 256, 1);
    ln_kernel<<<LN_BLOCKS, 256>>>(pq, pk, nullptr, nullptr, declns, declnb, ROWS);
    linear_kernel<<<dim3(ROWS / 64, NEE / 64), 256>>>(pk, linw, linb, plog);

    if (out_size >= SCORE_SIZE) {
        dim3 sg(16, 16, 16);
        score_kernel<<<sg, 256>>>(plog, out, out_size);
    }
    int write_code = (out_size >= SCORE_SIZE + 1 + NROWS) ? 1 : 0;
    loss_argmax_kernel<<<(NROWS * 32) / 256, 256>>>(plog, ncode, prl, out, write_code);

    int loss_off = -1;
    if (out_size == 1) loss_off = 0;
    else if (out_size > SCORE_SIZE) loss_off = SCORE_SIZE;
    if (loss_off >= 0)
        loss_reduce_kernel<<<1, 256>>>(prl, out, loss_off);
}

// round 17
// speedup vs baseline: 1.5893x; 1.3033x over previous
#include <cuda_runtime.h>
#include <cuda_fp16.h>
#include <math.h>

// ---------------------------------------------------------------------------
// Problem constants
// ---------------------------------------------------------------------------
#define BB    4
#define BPTT  16
#define PRED  4
#define SS    20
#define VV    512
#define EE    256
#define NHH   8
#define HEADD 32
#define HIDD  512
#define NEE   512
#define FF    80

#define FVE   ((size_t)FF * VV * EE)
#define FVH   ((size_t)FF * VV * HIDD)
#define SCORE_SIZE (BB * NEE * PRED * VV)
#define NROWS (BB * PRED * VV)

#define WEE27 1769472ull                 // 27*256*256
#define WEH27 3538944ull                 // 27*256*512
#define WT_LAYER (4ull*WEE27 + 2ull*WEH27)
#define WT_TOTAL (4ull*WT_LAYER + WEE27)

// ---------------------------------------------------------------------------
// Scratch (allocation-free: __device__ globals)
// ---------------------------------------------------------------------------
__device__ float g_x[FVE];
__device__ float g_q[FVE];
__device__ float g_k[FVE];
__device__ float g_v[FVE];
__device__ float g_logits[FVH];
__device__ float g_rowloss[NROWS];
__device__ __half g_ah[FVE];
__device__ __half g_al[FVE];
__device__ __half g_bh[FVH];
__device__ __half g_bl[FVH];
__device__ __half g_wth[WT_TOTAL];
__device__ __half g_wtl[WT_TOTAL];

// ---------------------------------------------------------------------------
// PTX helpers (baseline sm_103-compatible: cp.async, ldmatrix, mma.sync)
// ---------------------------------------------------------------------------
__device__ __forceinline__ unsigned smem_u32(const void* p) {
    unsigned a;
    asm("{ .reg .u64 t; cvta.to.shared.u64 t, %1; cvt.u32.u64 %0, t; }"
        : "=r"(a) : "l"(p));
    return a;
}
__device__ __forceinline__ void cp_async16(unsigned dst, const void* src) {
    asm volatile("cp.async.cg.shared.global [%0], [%1], 16;"
                 :: "r"(dst), "l"(src) : "memory");
}
__device__ __forceinline__ void ldsm4(unsigned* r, unsigned addr) {
    asm volatile("ldmatrix.sync.aligned.m8n8.x4.shared.b16 {%0,%1,%2,%3}, [%4];"
                 : "=r"(r[0]), "=r"(r[1]), "=r"(r[2]), "=r"(r[3]) : "r"(addr));
}
__device__ __forceinline__ void mma16816(float* d, const unsigned* a, const unsigned* b) {
    asm volatile(
        "mma.sync.aligned.m16n8k16.row.col.f32.f16.f16.f32 "
        "{%0,%1,%2,%3}, {%4,%5,%6,%7}, {%8,%9}, {%0,%1,%2,%3};"
        : "+f"(d[0]), "+f"(d[1]), "+f"(d[2]), "+f"(d[3])
        : "r"(a[0]), "r"(a[1]), "r"(a[2]), "r"(a[3]), "r"(b[0]), "r"(b[1]));
}

// ---------------------------------------------------------------------------
// Weight transpose + fp16 split, ALL weights in one launch (also makes ncu's
// "-s 5" land on a conv launch). dst layout per region: [27][Cout][Cin] hi/lo.
// ---------------------------------------------------------------------------
__global__ void wconv_all_kernel(const float* __restrict__ wq, const float* __restrict__ wk,
                                 const float* __restrict__ wv, const float* __restrict__ wo,
                                 const float* __restrict__ w1, const float* __restrict__ w2,
                                 const float* __restrict__ decw,
                                 __half* __restrict__ th, __half* __restrict__ tl)
{
    size_t i = (size_t)blockIdx.x * 256 + threadIdx.x;
    if (i >= WT_TOTAL) return;
    const float* src; size_t rr; int Cin, Cout;
    if (i < 4ull * WT_LAYER) {
        int layer = (int)(i / WT_LAYER);
        size_t r = i - (size_t)layer * WT_LAYER;
        if (r < 4ull * WEE27) {
            int which = (int)(r / WEE27);
            rr = r - (size_t)which * WEE27;
            Cin = 256; Cout = 256;
            const float* base[4] = {wq, wk, wv, wo};
            src = base[which] + (size_t)layer * WEE27;
        } else if (r < 4ull * WEE27 + WEH27) {
            rr = r - 4ull * WEE27;
            Cin = 256; Cout = 512;
            src = w1 + (size_t)layer * WEH27;
        } else {
            rr = r - 4ull * WEE27 - WEH27;
            Cin = 512; Cout = 256;
            src = w2 + (size_t)layer * WEH27;
        }
    } else {
        rr = i - 4ull * WT_LAYER;
        Cin = 256; Cout = 256;
        src = decw;
    }
    int pc = Cin * Cout;
    int o = (int)(rr / pc);
    int r2 = (int)(rr - (size_t)o * pc);
    int co = r2 / Cin, ci = r2 - co * Cin;
    float x = src[((size_t)o * Cin + ci) * Cout + co];
    __half h = __float2half(x);
    th[i] = h;
    tl[i] = __float2half(x - __half2float(h));
}

// ---------------------------------------------------------------------------
// Embedding
// ---------------------------------------------------------------------------
__global__ void embed_kernel(const int* __restrict__ code,
                             const float* __restrict__ emb,
                             const float* __restrict__ pos,
                             float* __restrict__ x)
{
    size_t idx = (size_t)blockIdx.x * blockDim.x + threadIdx.x;
    if (idx >= FVE) return;
    int e = (int)(idx & 255);
    int v = (int)((idx >> 8) & 511);
    int f = (int)(idx >> 17);
    int b = f / SS, s = f % SS;
    int tok = (s < BPTT) ? code[((b * BPTT + s) << 9) + v] : NEE;
    x[idx] = emb[tok * EE + e] + pos[s * EE + e];
}

// ---------------------------------------------------------------------------
// LayerNorm; writes f32 and/or fp16 hi/lo pair
// ---------------------------------------------------------------------------
__global__ void ln_kernel(const float* __restrict__ in,
                          float* __restrict__ outF,
                          __half* __restrict__ outH,
                          __half* __restrict__ outL,
                          const float* __restrict__ sc, const float* __restrict__ bi,
                          int rows)
{
    int wid  = (int)((blockIdx.x * blockDim.x + threadIdx.x) >> 5);
    int lane = threadIdx.x & 31;
    if (wid >= rows) return;
    const float* p = in + (size_t)wid * EE;
    float v8[8];
    float s = 0.f, sq = 0.f;
#pragma unroll
    for (int i = 0; i < 8; ++i) {
        float xv = p[lane + i * 32];
        v8[i] = xv; s += xv; sq = fmaf(xv, xv, sq);
    }
#pragma unroll
    for (int off = 16; off > 0; off >>= 1) {
        s  += __shfl_xor_sync(0xffffffffu, s, off);
        sq += __shfl_xor_sync(0xffffffffu, sq, off);
    }
    float m   = s * (1.f / 256.f);
    float var = sq * (1.f / 256.f) - m * m;
    if (var < 0.f) var = 0.f;
    float inv = rsqrtf(var + 1e-5f);
#pragma unroll
    for (int i = 0; i < 8; ++i) {
        int e = lane + i * 32;
        float r = (v8[i] - m) * inv * sc[e] + bi[e];
        size_t oi = (size_t)wid * EE + e;
        if (outF) outF[oi] = r;
        if (outH) {
            __half h = __float2half(r);
            outH[oi] = h;
            outL[oi] = __float2half(r - __half2float(h));
        }
    }
}

// ---------------------------------------------------------------------------
// Tensor-core (mma.sync fp16) 3D conv, 3x3x3 SAME, fp16x3 split precision,
// per-chunk RN accumulator drain; PADDED-VOLUME A REUSE: a zero-padded
// 10x10x4 activation volume (cin-chunk 32, hi+lo) is staged ONCE per
// cin-group and all 27 taps read it via ldmatrix with a uniform shifted
// offset -- A cp.async traffic drops 27x. B tiles stay double-buffered
// cp.async pipelined. 2 CTAs/SM (84.5KB smem, 128-reg cap).
//   CTA: 256 thr (8 warps), tile M=128 x N=64; warp tile 32x32.
//   K loop: cin-groups of 32 (outer) x 27 taps (inner), 2 k16 steps each.
// ---------------------------------------------------------------------------
#define AVROW 80                            // bytes stride per volume row (64B data)
#define AVH_OFF 0
#define AVL_OFF (400 * AVROW)               // 32000
#define AV_TOTAL (2 * 400 * AVROW)          // 64000
#define BROW 80
#define B_HALF (64 * BROW)                  // 5120
#define BSTG (2 * B_HALF)                   // 10240 (hi + lo)
#define BB_OFF AV_TOTAL
#define TC_SMEM_BYTES (AV_TOTAL + 2 * BSTG) // 84480

__global__ void __launch_bounds__(256, 2)
conv3d_mma_kernel(const __half* __restrict__ xh,
                  const __half* __restrict__ xl,
                  const __half* __restrict__ wth,
                  const __half* __restrict__ wtl,
                  const float* __restrict__ bias, const float* __restrict__ residual,
                  float* __restrict__ yf,
                  __half* __restrict__ yh, __half* __restrict__ yl,
                  int Cin, int Cout, int do_gelu)
{
    extern __shared__ char smem[];
    unsigned sb = smem_u32(smem);
    const int t = threadIdx.x, w = t >> 5, lane = t & 31;
    const int wm = w & 3, wn = w >> 2;
    const int f = blockIdx.x, co0 = blockIdx.y * 64;
    const int zbase = blockIdx.z * 2, v0 = blockIdx.z * 128;

    // B staging map: thread t -> cout row t/4, 16B quad t&3
    const int brow = t >> 2, bq = t & 3;

    float acc[2][4][4], mst[2][4][4];
#pragma unroll
    for (int mt = 0; mt < 2; ++mt)
#pragma unroll
        for (int nt = 0; nt < 4; ++nt)
#pragma unroll
            for (int q = 0; q < 4; ++q) { acc[mt][nt][q] = 0.f; mst[mt][nt][q] = 0.f; }

    // ---- A ldmatrix per-lane base addresses into the padded volume
    const int rA = ((lane >> 3) & 1) * 8 + (lane & 7);
    const int cA = (lane >> 4) * 16;
    unsigned aA0h[2], aA0l[2];
#pragma unroll
    for (int mt = 0; mt < 2; ++mt) {
        int m = wm * 32 + mt * 16 + rA;
        int v = v0 + m;
        int vz = v >> 6, vy = (v >> 3) & 7, vx = v & 7;
        int p0 = (vz - zbase + 1) * 100 + (vy + 1) * 10 + (vx + 1);
        aA0h[mt] = sb + AVH_OFF + (unsigned)(p0 * AVROW) + cA;
        aA0l[mt] = sb + AVL_OFF + (unsigned)(p0 * AVROW) + cA;
    }
    // ---- B ldmatrix lane offsets (relative to stage base)
    const int rB = ((lane >> 4) & 1) * 8 + (lane & 7);
    const int cB = ((lane >> 3) & 1) * 16;
    unsigned oBh[2], oBl[2];
#pragma unroll
    for (int nt2 = 0; nt2 < 2; ++nt2) {
        unsigned off = (unsigned)(wn * 32 + nt2 * 16 + rB) * BROW + cB;
        oBh[nt2] = off;
        oBl[nt2] = B_HALF + off;
    }

    const int ncc = Cin >> 5;             // cin-groups of 32
    const int nchunks = 27 * ncc;         // cc-major: ch = cc*27 + o

    // ---- helpers
    auto stage_AV = [&](int cc) {         // stage padded volume for cin-group cc
        for (int r = t; r < 400; r += 256) {
            int pz = r / 100, rem = r - pz * 100;
            int py = rem / 10, px = rem - py * 10;
            int gz = zbase + pz - 1, gy = py - 1, gx = px - 1;
            if ((unsigned)gz < 8u && (unsigned)gy < 8u && (unsigned)gx < 8u) {
                size_t abase = ((size_t)f * VV + (size_t)(gz * 64 + gy * 8 + gx)) * Cin
                               + (size_t)cc * 32;
                unsigned dh = sb + AVH_OFF + (unsigned)(r * AVROW);
                unsigned dl = sb + AVL_OFF + (unsigned)(r * AVROW);
#pragma unroll
                for (int i = 0; i < 4; ++i) {
                    cp_async16(dh + i * 16, xh + abase + i * 8);
                    cp_async16(dl + i * 16, xl + abase + i * 8);
                }
            }
        }
    };
    auto stage_B = [&](int ch, unsigned sbase) {
        int cc = ch / 27, o = ch - cc * 27;
        size_t bbase = ((size_t)o * Cout + (size_t)(co0 + brow)) * Cin + (size_t)cc * 32;
        cp_async16(sbase + (unsigned)brow * BROW + bq * 16, wth + bbase + bq * 8);
        cp_async16(sbase + B_HALF + (unsigned)brow * BROW + bq * 16, wtl + bbase + bq * 8);
    };

    // ---- zero the padded volume (halo rows stay zero forever)
    {
        uint4 z = make_uint4(0, 0, 0, 0);
        for (int i = t; i < AV_TOTAL / 16; i += 256)
            ((uint4*)smem)[i] = z;
    }
    __syncthreads();

    // ---- prologue: AV(0) and B(0)
    stage_AV(0);
    asm volatile("cp.async.commit_group;" ::: "memory");
    stage_B(0, sb + BB_OFF);
    asm volatile("cp.async.commit_group;" ::: "memory");

    for (int ch = 0; ch < nchunks; ++ch) {
        int o = ch % 27;
        if (ch + 1 < nchunks) {
            stage_B(ch + 1, sb + BB_OFF + (unsigned)((ch + 1) & 1) * BSTG);
            asm volatile("cp.async.commit_group;" ::: "memory");
            asm volatile("cp.async.wait_group 1;" ::: "memory");
        } else {
            asm volatile("cp.async.wait_group 0;" ::: "memory");
        }
        __syncthreads();

        unsigned bbuf = sb + BB_OFF + (unsigned)(ch & 1) * BSTG;
        int dz = o / 9 - 1, rr = o % 9;
        int toff = (dz * 100 + (rr / 3 - 1) * 10 + (rr % 3 - 1)) * AVROW;

        // ---- compute: 2 k16 steps x (2 mt x 4 nt) x 3 terms
#pragma unroll
        for (int ks = 0; ks < 2; ++ks) {
            unsigned kb = (unsigned)ks * 32;
            unsigned fAh[2][4], fAl[2][4], fBh[4][2], fBl[4][2];
#pragma unroll
            for (int mt = 0; mt < 2; ++mt) {
                ldsm4(fAh[mt], aA0h[mt] + toff + kb);
                ldsm4(fAl[mt], aA0l[mt] + toff + kb);
            }
#pragma unroll
            for (int nt2 = 0; nt2 < 2; ++nt2) {
                unsigned r4[4];
                ldsm4(r4, bbuf + oBh[nt2] + kb);
                fBh[nt2 * 2][0] = r4[0]; fBh[nt2 * 2][1] = r4[1];
                fBh[nt2 * 2 + 1][0] = r4[2]; fBh[nt2 * 2 + 1][1] = r4[3];
                ldsm4(r4, bbuf + oBl[nt2] + kb);
                fBl[nt2 * 2][0] = r4[0]; fBl[nt2 * 2][1] = r4[1];
                fBl[nt2 * 2 + 1][0] = r4[2]; fBl[nt2 * 2 + 1][1] = r4[3];
            }
#pragma unroll
            for (int mt = 0; mt < 2; ++mt)
#pragma unroll
                for (int nt = 0; nt < 4; ++nt) {
                    mma16816(acc[mt][nt], fAh[mt], fBh[nt]);
                    mma16816(acc[mt][nt], fAl[mt], fBh[nt]);
                    mma16816(acc[mt][nt], fAh[mt], fBl[nt]);
                }
        }
        // ---- drain: RN-add chunk partial into master
#pragma unroll
        for (int mt = 0; mt < 2; ++mt)
#pragma unroll
            for (int nt = 0; nt < 4; ++nt)
#pragma unroll
                for (int q = 0; q < 4; ++q) {
                    mst[mt][nt][q] += acc[mt][nt][q];
                    acc[mt][nt][q] = 0.f;
                }
        __syncthreads();

        // ---- at cin-group boundary: restage the volume (exposed; partner
        //      CTA on the SM computes meanwhile)
        if (o == 26 && ch + 1 < nchunks) {
            stage_AV((ch + 1) / 27);
            asm volatile("cp.async.commit_group;" ::: "memory");
        }
    }

    // ---- epilogue
    const int mrow0 = wm * 32 + (lane >> 2);
    const int ncol0 = (lane & 3) * 2;
#pragma unroll
    for (int mt = 0; mt < 2; ++mt)
#pragma unroll
        for (int half = 0; half < 2; ++half) {
            int m = mrow0 + mt * 16 + half * 8;
            int v = v0 + m;
            size_t rowbase = ((size_t)f * VV + v) * Cout;
#pragma unroll
            for (int nt = 0; nt < 4; ++nt) {
                int col = co0 + wn * 32 + nt * 8 + ncol0;
                size_t oi = rowbase + col;
                float r0 = mst[mt][nt][half * 2 + 0] + bias[col];
                float r1 = mst[mt][nt][half * 2 + 1] + bias[col + 1];
                if (residual) { r0 += residual[oi]; r1 += residual[oi + 1]; }
                if (do_gelu) {
                    r0 = 0.5f * r0 * (1.f + erff(r0 * 0.7071067811865475f));
                    r1 = 0.5f * r1 * (1.f + erff(r1 * 0.7071067811865475f));
                }
                if (yf) { yf[oi] = r0; yf[oi + 1] = r1; }
                if (yh) {
                    __half h0 = __float2half(r0);
                    __half h1 = __float2half(r1);
                    yh[oi] = h0; yh[oi + 1] = h1;
                    yl[oi]     = __float2half(r0 - __half2float(h0));
                    yl[oi + 1] = __float2half(r1 - __half2float(h1));
                }
            }
        }
}

// ---------------------------------------------------------------------------
// Attention over time (20 steps) per (b, voxel, head). Writes fp16 hi/lo.
// ---------------------------------------------------------------------------
__global__ void __launch_bounds__(128)
attn_kernel(const float* __restrict__ q, const float* __restrict__ k,
            const float* __restrict__ v,
            __half* __restrict__ oh, __half* __restrict__ ol)
{
    __shared__ float sm[4][2380];
    int wlocal = threadIdx.x >> 5;
    int lane   = threadIdx.x & 31;
    int wid    = blockIdx.x * 4 + wlocal;
    int h  = wid & 7;
    int vx = (wid >> 3) & 511;
    int b  = wid >> 12;

    float* qs = sm[wlocal];
    float* ks = qs + 660;
    float* vs = ks + 660;
    float* at = vs + 660;

    size_t base = (size_t)vx * EE + h * HEADD + lane;
#pragma unroll
    for (int s = 0; s < SS; ++s) {
        size_t gi = (size_t)(b * SS + s) * (VV * EE) + base;
        qs[s * 33 + lane] = q[gi];
        ks[s * 33 + lane] = k[gi];
        vs[s * 33 + lane] = v[gi];
    }
    __syncwarp();

    const float scale = 0.17677669529663687f;
    int tt = lane;
#pragma unroll 1
    for (int s = 0; s < SS; ++s) {
        float sc = -1e30f;
        if (tt < SS) {
            float a = 0.f;
#pragma unroll
            for (int d = 0; d < HEADD; ++d)
                a = fmaf(qs[s * 33 + d], ks[tt * 33 + d], a);
            sc = a * scale;
        }
        float m = sc;
#pragma unroll
        for (int off = 16; off > 0; off >>= 1)
            m = fmaxf(m, __shfl_xor_sync(0xffffffffu, m, off));
        float e = (tt < SS) ? expf(sc - m) : 0.f;
        float su = e;
#pragma unroll
        for (int off = 16; off > 0; off >>= 1)
            su += __shfl_xor_sync(0xffffffffu, su, off);
        if (tt < SS) at[s * SS + tt] = e / su;
    }
    __syncwarp();

#pragma unroll 1
    for (int s = 0; s < SS; ++s) {
        float a = 0.f;
#pragma unroll
        for (int t2 = 0; t2 < SS; ++t2)
            a = fmaf(at[s * SS + t2], vs[t2 * 33 + lane], a);
        size_t gi = (size_t)(b * SS + s) * (VV * EE) + base;
        __half hb = __float2half(a);
        oh[gi] = hb;
        ol[gi] = __float2half(a - __half2float(hb));
    }
}

// ---------------------------------------------------------------------------
// Final linear: [40960 x 256] @ [256 x 512] + bias
// ---------------------------------------------------------------------------
__global__ void __launch_bounds__(256)
linear_kernel(const float* __restrict__ A, const float* __restrict__ Bw,
              const float* __restrict__ bias, float* __restrict__ C)
{
    __shared__ float As[32 * 65];
    __shared__ float Bs[32 * 64];
    int t  = threadIdx.x;
    int tx = t & 15, ty = t >> 4;
    int m0 = blockIdx.x * 64, n0 = blockIdx.y * 64;
    float acc[4][4];
#pragma unroll
    for (int i = 0; i < 4; ++i)
#pragma unroll
        for (int j = 0; j < 4; ++j) acc[i][j] = 0.f;

    for (int kt = 0; kt < 8; ++kt) {
        for (int i = t; i < 2048; i += 256) {
            int r = i >> 5, kk = i & 31;
            As[kk * 65 + r] = A[(size_t)(m0 + r) * EE + kt * 32 + kk];
        }
        for (int i = t; i < 2048; i += 256) {
            int kk = i >> 6, c = i & 63;
            Bs[kk * 64 + c] = Bw[(size_t)(kt * 32 + kk) * NEE + n0 + c];
        }
        __syncthreads();
#pragma unroll
        for (int kk = 0; kk < 32; ++kk) {
            float a[4];
#pragma unroll
            for (int i = 0; i < 4; ++i) a[i] = As[kk * 65 + ty * 4 + i];
            float4 bvv = *(const float4*)&Bs[kk * 64 + tx * 4];
            float bvals[4] = {bvv.x, bvv.y, bvv.z, bvv.w};
#pragma unroll
            for (int i = 0; i < 4; ++i)
#pragma unroll
                for (int j = 0; j < 4; ++j)
                    acc[i][j] = fmaf(a[i], bvals[j], acc[i][j]);
        }
        __syncthreads();
    }
#pragma unroll
    for (int i = 0; i < 4; ++i)
#pragma unroll
        for (int j = 0; j < 4; ++j)
            C[(size_t)(m0 + ty * 4 + i) * NEE + n0 + tx * 4 + j] =
                acc[i][j] + bias[n0 + tx * 4 + j];
}

// ---------------------------------------------------------------------------
// Score transpose
// ---------------------------------------------------------------------------
__global__ void score_kernel(const float* __restrict__ logits, float* __restrict__ out,
                             int out_size)
{
    __shared__ float tile[32][33];
    int bp = blockIdx.z;
    int b = bp >> 2, p = bp & 3;
    int v0 = blockIdx.x * 32, c0 = blockIdx.y * 32;
    int f = b * SS + BPTT + p;
    int t = threadIdx.x;
    int ci = t & 31, vi = t >> 5;
#pragma unroll
    for (int r = 0; r < 32; r += 8)
        tile[vi + r][ci] = logits[((size_t)f * VV + v0 + vi + r) * NEE + c0 + ci];
    __syncthreads();
    int vv2 = t & 31, cc = t >> 5;
#pragma unroll
    for (int r = 0; r < 32; r += 8) {
        size_t oidx = (((size_t)(b * NEE + c0 + cc + r)) * PRED + p) * VV + v0 + vv2;
        if (oidx < (size_t)out_size) out[oidx] = tile[vv2][cc + r];
    }
}

// ---------------------------------------------------------------------------
// Loss + argmax
// ---------------------------------------------------------------------------
__global__ void loss_argmax_kernel(const float* __restrict__ logits,
                                   const int* __restrict__ ncode,
                                   float* __restrict__ rowloss,
                                   float* __restrict__ out, int write_code)
{
    int wid  = (int)((blockIdx.x * blockDim.x + threadIdx.x) >> 5);
    int lane = threadIdx.x & 31;
    if (wid >= NROWS) return;
    int v = wid & 511, p = (wid >> 9) & 3, b = wid >> 11;
    const float* lp = logits + ((size_t)(b * SS + BPTT + p) * VV + v) * NEE;

    float vals[16];
    float mx = -1e30f;
    int mi = 0;
#pragma unroll
    for (int i = 0; i < 16; ++i) {
        int c = lane + i * 32;
        float xv = lp[c];
        vals[i] = xv;
        if (xv > mx) { mx = xv; mi = c; }
    }
#pragma unroll
    for (int off = 16; off > 0; off >>= 1) {
        float om = __shfl_xor_sync(0xffffffffu, mx, off);
        int   oi = __shfl_xor_sync(0xffffffffu, mi, off);
        if (om > mx || (om == mx && oi < mi)) { mx = om; mi = oi; }
    }
    float se = 0.f;
#pragma unroll
    for (int i = 0; i < 16; ++i) se += expf(vals[i] - mx);
#pragma unroll
    for (int off = 16; off > 0; off >>= 1)
        se += __shfl_xor_sync(0xffffffffu, se, off);

    int tgt = ncode[wid];
    if (lane == (tgt & 31))
        rowloss[wid] = -(vals[tgt >> 5] - mx - logf(se));
    if (write_code && lane == 0)
        out[(size_t)SCORE_SIZE + 1 + wid] = (float)mi;
}

__global__ void loss_reduce_kernel(const float* __restrict__ rowloss,
                                   float* __restrict__ out, int loss_off)
{
    __shared__ float smr[256];
    int t = threadIdx.x;
    float a = 0.f;
    for (int i = t; i < NROWS; i += 256) a += rowloss[i];
    smr[t] = a;
    __syncthreads();
    for (int s = 128; s > 0; s >>= 1) {
        if (t < s) smr[t] += smr[t + s];
        __syncthreads();
    }
    if (t == 0) out[loss_off] = smr[0] * (1.f / (float)NROWS);
}

// ---------------------------------------------------------------------------
// Orchestration
// ---------------------------------------------------------------------------
extern "C" void kernel_launch(void* const* d_in, const int* in_sizes, int n_in,
                              void* d_out, int out_size)
{
    (void)in_sizes; (void)n_in;
    const int*   code   = (const int*)  d_in[0];
    const int*   ncode  = (const int*)  d_in[1];
    const float* emb    = (const float*)d_in[2];
    const float* pos    = (const float*)d_in[3];
    const float* ln1s   = (const float*)d_in[4];
    const float* ln1b   = (const float*)d_in[5];
    const float* ln2s   = (const float*)d_in[6];
    const float* ln2b   = (const float*)d_in[7];
    const float* wq     = (const float*)d_in[8];
    const float* bq     = (const float*)d_in[9];
    const float* wk     = (const float*)d_in[10];
    const float* bk     = (const float*)d_in[11];
    const float* wv     = (const float*)d_in[12];
    const float* bv     = (const float*)d_in[13];
    const float* wo     = (const float*)d_in[14];
    const float* bo     = (const float*)d_in[15];
    const float* w1     = (const float*)d_in[16];
    const float* b1     = (const float*)d_in[17];
    const float* w2     = (const float*)d_in[18];
    const float* b2     = (const float*)d_in[19];
    const float* lnfs   = (const float*)d_in[20];
    const float* lnfb   = (const float*)d_in[21];
    const float* decw   = (const float*)d_in[22];
    const float* decb   = (const float*)d_in[23];
    const float* declns = (const float*)d_in[24];
    const float* declnb = (const float*)d_in[25];
    const float* linw   = (const float*)d_in[26];
    const float* linb   = (const float*)d_in[27];
    float* out = (float*)d_out;

    float *px, *pq, *pk, *pv, *plog, *prl;
    __half *pah, *pal, *pbh, *pbl, *pwh, *pwl;
    cudaGetSymbolAddress((void**)&px,   g_x);
    cudaGetSymbolAddress((void**)&pq,   g_q);
    cudaGetSymbolAddress((void**)&pk,   g_k);
    cudaGetSymbolAddress((void**)&pv,   g_v);
    cudaGetSymbolAddress((void**)&plog, g_logits);
    cudaGetSymbolAddress((void**)&prl,  g_rowloss);
    cudaGetSymbolAddress((void**)&pah,  g_ah);
    cudaGetSymbolAddress((void**)&pal,  g_al);
    cudaGetSymbolAddress((void**)&pbh,  g_bh);
    cudaGetSymbolAddress((void**)&pbl,  g_bl);
    cudaGetSymbolAddress((void**)&pwh,  g_wth);
    cudaGetSymbolAddress((void**)&pwl,  g_wtl);

    cudaFuncSetAttribute(conv3d_mma_kernel,
                         cudaFuncAttributeMaxDynamicSharedMemorySize,
                         TC_SMEM_BYTES);

    const int ROWS = FF * VV;
    const int LN_BLOCKS = (ROWS * 32) / 256;

    // ---- convert + transpose ALL conv weights (one launch) ----
    wconv_all_kernel<<<(unsigned)((WT_TOTAL + 255) / 256), 256>>>(
        wq, wk, wv, wo, w1, w2, decw, pwh, pwl);

    embed_kernel<<<(int)((FVE + 255) / 256), 256>>>(code, emb, pos, px);

    dim3 cgE(FF, 4, 4);   // Cout=256
    dim3 cgH(FF, 8, 4);   // Cout=512
    for (int i = 0; i < 4; ++i) {
        size_t base = (size_t)i * WT_LAYER;
        ln_kernel<<<LN_BLOCKS, 256>>>(px, nullptr, pah, pal,
                                      ln1s + i * EE, ln1b + i * EE, ROWS);
        conv3d_mma_kernel<<<cgE, 256, TC_SMEM_BYTES>>>(pah, pal,
            pwh + base + 0 * WEE27, pwl + base + 0 * WEE27,
            bq + i * EE, nullptr, pq, nullptr, nullptr, 256, 256, 0);
        conv3d_mma_kernel<<<cgE, 256, TC_SMEM_BYTES>>>(pah, pal,
            pwh + base + 1 * WEE27, pwl + base + 1 * WEE27,
            bk + i * EE, nullptr, pk, nullptr, nullptr, 256, 256, 0);
        conv3d_mma_kernel<<<cgE, 256, TC_SMEM_BYTES>>>(pah, pal,
            pwh + base + 2 * WEE27, pwl + base + 2 * WEE27,
            bv + i * EE, nullptr, pv, nullptr, nullptr, 256, 256, 0);
        attn_kernel<<<4096, 128>>>(pq, pk, pv, pah, pal);
        conv3d_mma_kernel<<<cgE, 256, TC_SMEM_BYTES>>>(pah, pal,
            pwh + base + 3 * WEE27, pwl + base + 3 * WEE27,
            bo + i * EE, px, px, nullptr, nullptr, 256, 256, 0);
        ln_kernel<<<LN_BLOCKS, 256>>>(px, nullptr, pah, pal,
                                      ln2s + i * EE, ln2b + i * EE, ROWS);
        conv3d_mma_kernel<<<cgH, 256, TC_SMEM_BYTES>>>(pah, pal,
            pwh + base + 4 * WEE27, pwl + base + 4 * WEE27,
            b1 + i * HIDD, nullptr, nullptr, pbh, pbl, 256, 512, 1);
        conv3d_mma_kernel<<<cgE, 256, TC_SMEM_BYTES>>>(pbh, pbl,
            pwh + base + 4 * WEE27 + WEH27, pwl + base + 4 * WEE27 + WEH27,
            b2 + i * EE, px, px, nullptr, nullptr, 512, 256, 0);
    }

    const size_t offdec = 4 * WT_LAYER;
    ln_kernel<<<LN_BLOCKS, 256>>>(px, nullptr, pah, pal, lnfs, lnfb, ROWS);
    conv3d_mma_kernel<<<cgE, 256, TC_SMEM_BYTES>>>(pah, pal,
        pwh + offdec, pwl + offdec, decb, nullptr, pq, nullptr, nullptr, 256, 256, 1);
    ln_kernel<<<LN_BLOCKS, 256>>>(pq, pk, nullptr, nullptr, declns, declnb, ROWS);
    linear_kernel<<<dim3(ROWS / 64, NEE / 64), 256>>>(pk, linw, linb, plog);

    if (out_size >= SCORE_SIZE) {
        dim3 sg(16, 16, 16);
        score_kernel<<<sg, 256>>>(plog, out, out_size);
    }
    int write_code = (out_size >= SCORE_SIZE + 1 + NROWS) ? 1 : 0;
    loss_argmax_kernel<<<(NROWS * 32) / 256, 256>>>(plog, ncode, prl, out, write_code);

    int loss_off = -1;
    if (out_size == 1) loss_off = 0;
    else if (out_size > SCORE_SIZE) loss_off = SCORE_SIZE;
    if (loss_off >= 0)
        loss_reduce_kernel<<<1, 256>>>(prl, out, loss_off);
}